// round 2
// baseline (speedup 1.0000x reference)
#include <cuda_runtime.h>
#include <cstdint>
#include <cstddef>

#define BB   64
#define WW   254
#define SS   256
#define DPHO 768
#define DIN  968
#define HH   256
#define ROWS (BB*WW)   // 16256

// ---------------- scratch (static device globals; no allocation) ------------
__device__ float g_emb[(size_t)ROWS * DIN];    // [row][968]
__device__ float g_xp [(size_t)ROWS * 2048];   // [row][dir*1024 + gate*256 + j]
__device__ float g_h  [2][2][BB][HH];          // [dir][phase][b][j]

// ---------------- packed f32x2 helpers (sm_103a FFMA2 path) -----------------
__device__ __forceinline__ unsigned long long pack2(float x, float y) {
    unsigned long long r;
    asm("mov.b64 %0, {%1, %2};" : "=l"(r) : "f"(x), "f"(y));
    return r;
}
__device__ __forceinline__ void unpack2(unsigned long long v, float& lo, float& hi) {
    asm("mov.b64 {%0, %1}, %2;" : "=f"(lo), "=f"(hi) : "l"(v));
}
__device__ __forceinline__ void fma2(unsigned long long& d, unsigned long long a, unsigned long long b) {
    asm("fma.rn.f32x2 %0, %1, %2, %0;" : "+l"(d) : "l"(a), "l"(b));
}

// L1-bypassing vector load (reads L2 directly; needed for cross-CTA h exchange)
__device__ __forceinline__ float4 ldcv4(const float* p) {
    float4 v;
    asm volatile("ld.global.cv.v4.f32 {%0,%1,%2,%3}, [%4];"
                 : "=f"(v.x), "=f"(v.y), "=f"(v.z), "=f"(v.w) : "l"(p));
    return v;
}

__device__ __forceinline__ float sigmoidf(float x) {
    return 1.0f / (1.0f + __expf(-x));
}
__device__ __forceinline__ float tanh_fast(float x) {
    return 1.0f - 2.0f / (__expf(2.0f * x) + 1.0f);
}

__device__ __forceinline__ void cluster_sync_all() {
    asm volatile("barrier.cluster.arrive.aligned;" ::: "memory");
    asm volatile("barrier.cluster.wait.aligned;"   ::: "memory");
}

// ============================================================================
// Kernel A: emb[row][968] = [word_emb(100) | span_sum_pho(768) | pos_emb(100)]
// one block per (b,w) row, 256 threads
// ============================================================================
__global__ void embed_kernel(const int* __restrict__ words,
                             const float* __restrict__ features,
                             const int* __restrict__ lip,
                             const int* __restrict__ postags,
                             const float* __restrict__ word_table,
                             const float* __restrict__ pos_table) {
    int row = blockIdx.x;
    int b = row / WW, w = row % WW;
    int t = threadIdx.x;
    float* er = g_emb + (size_t)row * DIN;

    if (t < 25) {                       // word embedding: 100 floats = 25 f4
        int wid = words[row];
        ((float4*)er)[t] = ((const float4*)(word_table + (size_t)wid * 100))[t];
    } else if (t >= 32 && t < 57) {     // pos embedding at offset 868
        int pid = postags[row];
        ((float4*)(er + 868))[t - 32] = ((const float4*)(pos_table + (size_t)pid * 100))[t - 32];
    }
    if (t >= 64) {                      // pho span sum: 768 floats = 192 f4
        int d4 = t - 64;                 // 0..191
        int lo = lip[b * (WW + 2) + w];
        int hi = lip[b * (WW + 2) + w + 1];
        if (lo < 0) lo = 0;
        if (hi > SS) hi = SS;
        float4 acc = make_float4(0.f, 0.f, 0.f, 0.f);
        for (int tok = lo; tok < hi; ++tok) {
            float4 f = ((const float4*)(features + ((size_t)b * SS + tok) * DPHO))[d4];
            acc.x += f.x; acc.y += f.y; acc.z += f.z; acc.w += f.w;
        }
        ((float4*)(er + 100))[d4] = acc;
    }
}

// ============================================================================
// Kernel B: xp[row][col] = emb[row][:] . w_ih[col mod 1024][:] + bias
// fp32 tiled GEMM with packed f32x2 FMA. 128x128 tile, BK=8, 256 thr, 8x8/thr.
// ============================================================================
#define GM 128
#define GN 128
#define GK 8

__global__ void __launch_bounds__(256, 2)
gemm_main(const float* __restrict__ wf, const float* __restrict__ wb,
          const float* __restrict__ bf, const float* __restrict__ bbias) {
    __shared__ float As[GK][GM];
    __shared__ float Bs[GK][GN];

    int row0    = blockIdx.x * GM;       // 127 tiles
    int colbase = blockIdx.y * GN;       // 16 tiles over 2048 cols
    int dir = colbase >> 10;
    int g0  = colbase & 1023;
    const float* wmat = dir ? wb : wf;
    const float* bias = dir ? bbias : bf;

    int tid = threadIdx.x;
    int tx = tid & 15, ty = tid >> 4;
    int lm = tid >> 1, lk = (tid & 1) * 4;

    unsigned long long c2[8][4];
#pragma unroll
    for (int i = 0; i < 8; i++)
#pragma unroll
        for (int j = 0; j < 4; j++) c2[i][j] = 0ULL;

    const float* aptr = g_emb + (size_t)(row0 + lm) * DIN + lk;
    const float* bptr = wmat  + (size_t)(g0  + lm) * DIN + lk;

    float4 a4 = *(const float4*)(aptr);
    float4 b4 = *(const float4*)(bptr);

    for (int k0 = 0; k0 < DIN; k0 += GK) {
        As[lk + 0][lm] = a4.x; As[lk + 1][lm] = a4.y;
        As[lk + 2][lm] = a4.z; As[lk + 3][lm] = a4.w;
        Bs[lk + 0][lm] = b4.x; Bs[lk + 1][lm] = b4.y;
        Bs[lk + 2][lm] = b4.z; Bs[lk + 3][lm] = b4.w;
        __syncthreads();
        if (k0 + GK < DIN) {            // prefetch next k-slab
            a4 = *(const float4*)(aptr + k0 + GK);
            b4 = *(const float4*)(bptr + k0 + GK);
        }
#pragma unroll
        for (int kk = 0; kk < GK; kk++) {
            float4 aA  = *(const float4*)&As[kk][ty * 8];
            float4 aBv = *(const float4*)&As[kk][ty * 8 + 4];
            const unsigned long long* bp = (const unsigned long long*)&Bs[kk][tx * 8];
            unsigned long long b2r[4];
            b2r[0] = bp[0]; b2r[1] = bp[1]; b2r[2] = bp[2]; b2r[3] = bp[3];
            float av[8] = {aA.x, aA.y, aA.z, aA.w, aBv.x, aBv.y, aBv.z, aBv.w};
#pragma unroll
            for (int i = 0; i < 8; i++) {
                unsigned long long ad = pack2(av[i], av[i]);
#pragma unroll
                for (int j = 0; j < 4; j++) fma2(c2[i][j], ad, b2r[j]);
            }
        }
        __syncthreads();
    }

    float bv[8];
#pragma unroll
    for (int j = 0; j < 8; j++) bv[j] = bias[g0 + tx * 8 + j];
#pragma unroll
    for (int i = 0; i < 8; i++) {
        float o8[8];
#pragma unroll
        for (int j = 0; j < 4; j++) {
            float lo, hi; unpack2(c2[i][j], lo, hi);
            o8[2 * j] = lo + bv[2 * j]; o8[2 * j + 1] = hi + bv[2 * j + 1];
        }
        float* op = g_xp + (size_t)(row0 + ty * 8 + i) * 2048 + colbase + tx * 8;
        ((float4*)op)[0] = make_float4(o8[0], o8[1], o8[2], o8[3]);
        ((float4*)op)[1] = make_float4(o8[4], o8[5], o8[6], o8[7]);
    }
}

// ============================================================================
// Kernel C: bidirectional LSTM recurrence.
// 16 clusters x 8 CTAs. cluster c: dir = c&1, batches [8*(c>>1), +8).
// CTA rank r owns hidden slice [32r,32r+32) (=128 gate rows), w_hh in registers.
// h exchanged via L2 global double buffer (stores weak->L2; loads ld.global.cv
// to bypass possibly-stale L1) + barrier.cluster per step.
// ============================================================================
__global__ void __cluster_dims__(8, 1, 1) __launch_bounds__(512, 1)
lstm_kernel(const float* __restrict__ whf, const float* __restrict__ whb,
            float* __restrict__ out) {
    __shared__ float h_sh[8][HH];        // [b_local][j]
    __shared__ float scr[4][8][128];     // [kc][b_local][local gate row]

    unsigned r;
    asm("mov.u32 %0, %%cluster_ctarank;" : "=r"(r));
    int cid = blockIdx.x >> 3;
    int dir = cid & 1;
    int bg  = (cid >> 1) * 8;
    const float* wmat = dir ? whb : whf;

    int t  = threadIdx.x;
    int kc = t >> 7;            // k-chunk 0..3 (64 k each)
    int lr = t & 127;           // local gate row (gate = lr>>5, j = lr&31)
    int gr = (lr >> 5) * 256 + (int)r * 32 + (lr & 31);   // global gate row

    // w_hh chunk for (gr, kc) -> 32 packed u64 in registers
    unsigned long long w2[32];
    {
        const float4* wp = (const float4*)(wmat + (size_t)gr * HH + kc * 64);
#pragma unroll
        for (int i = 0; i < 16; i++) {
            float4 v = wp[i];
            w2[2 * i]     = pack2(v.x, v.y);
            w2[2 * i + 1] = pack2(v.z, v.w);
        }
    }

    // zero initial h (phase 0) for this CTA's batch
    if (t < HH) g_h[dir][0][bg + r][t] = 0.f;

    // activation-thread persistent state (threads 0..255)
    float c_state = 0.f;
    int ab = t >> 5;            // batch 0..7
    int aj = t & 31;            // local hidden j
    int b_glob = bg + ab;
    int jg = (int)r * 32 + aj;

    float* out_rnn = out;
    float* out_hx  = out + (size_t)ROWS * 512 + (size_t)dir * ROWS * 256;

    cluster_sync_all();

    for (int step = 0; step < WW; ++step) {
        int w  = dir ? (WW - 1 - step) : step;
        int rb = step & 1;      // read phase
        int wph = rb ^ 1;       // write phase

        // prefetch xp for activation threads (latency hidden behind matvec)
        float xq0 = 0.f, xq1 = 0.f, xq2 = 0.f, xq3 = 0.f;
        if (t < 256) {
            const float* xp = g_xp + ((size_t)b_glob * WW + w) * 2048 + dir * 1024 + jg;
            xq0 = xp[0]; xq1 = xp[256]; xq2 = xp[512]; xq3 = xp[768];
        }

        // load h_prev (all 8 batches, full H): 512 threads x float4, L1-bypass
        {
            int bl = t >> 6, j4 = (t & 63) * 4;
            float4 hv = ldcv4(&g_h[dir][rb][bg + bl][j4]);
            *(float4*)&h_sh[bl][j4] = hv;
        }
        __syncthreads();

        // matvec: for each batch, 64-length packed dot with register weights
#pragma unroll
        for (int b = 0; b < 8; b++) {
            const unsigned long long* hp = (const unsigned long long*)&h_sh[b][kc * 64];
            unsigned long long acc = 0ULL;
#pragma unroll
            for (int p = 0; p < 32; p++) fma2(acc, w2[p], hp[p]);
            float lo, hi; unpack2(acc, lo, hi);
            scr[kc][b][lr] = lo + hi;
        }
        __syncthreads();

        if (t < 256) {
            float gi = xq0, gf = xq1, gg = xq2, go = xq3;
#pragma unroll
            for (int k = 0; k < 4; k++) {
                gi += scr[k][ab][aj];
                gf += scr[k][ab][32 + aj];
                gg += scr[k][ab][64 + aj];
                go += scr[k][ab][96 + aj];
            }
            float i_s = sigmoidf(gi);
            float f_s = sigmoidf(gf);
            float g_t = tanh_fast(gg);
            float o_s = sigmoidf(go);
            c_state = f_s * c_state + i_s * g_t;
            float h = o_s * tanh_fast(c_state);

            g_h[dir][wph][b_glob][jg] = h;
            size_t rowbw = (size_t)b_glob * WW + w;
            out_rnn[rowbw * 512 + dir * 256 + jg] = h;
            out_hx[rowbw * 256 + jg] = h;
        }
        cluster_sync_all();
    }
}

// ============================================================================
extern "C" void kernel_launch(void* const* d_in, const int* in_sizes, int n_in,
                              void* d_out, int out_size) {
    const int*   words      = (const int*)d_in[0];
    const float* features   = (const float*)d_in[1];
    const int*   lip        = (const int*)d_in[2];
    const int*   postags    = (const int*)d_in[3];
    // d_in[4] chars, d_in[5] masks: unused
    const float* word_table = (const float*)d_in[6];
    const float* pos_table  = (const float*)d_in[7];
    const float* w_ih_f     = (const float*)d_in[8];
    const float* w_hh_f     = (const float*)d_in[9];
    const float* b_f        = (const float*)d_in[10];
    const float* w_ih_b     = (const float*)d_in[11];
    const float* w_hh_b     = (const float*)d_in[12];
    const float* b_b        = (const float*)d_in[13];
    float* out = (float*)d_out;

    embed_kernel<<<ROWS, 256>>>(words, features, lip, postags, word_table, pos_table);
    dim3 gg(ROWS / GM, 2048 / GN);
    gemm_main<<<gg, 256>>>(w_ih_f, w_ih_b, b_f, b_b);
    lstm_kernel<<<128, 512>>>(w_hh_f, w_hh_b, out);
}